// round 13
// baseline (speedup 1.0000x reference)
#include <cuda_runtime.h>
#include <math.h>

#define H 1024
#define W 1024
#define BATCH 16
#define CH 3
#define NPLANE (H * W)
#define NPIX (BATCH * NPLANE)

#define G0 0.13533528323661270f  /* exp(-2)   */
#define G1 0.60653065971263342f  /* exp(-0.5) */
#define T1C 0.41421356237f       /* tan(22.5 deg) */
#define T2C 2.41421356237f       /* tan(67.5 deg) */
#define BANDEPS 1e-3f
#define WEDGE   1e-4f            /* near-pi wedge (ref wraps past 180) */

#define TX 128      /* tile width (outputs)  */
#define TY 64       /* tile height (outputs) */
#define NT 160      /* threads per block     */
#define LW 136      /* img row width loaded  : cols x0-4 .. x0+131 */
#define BW 132      /* blurred row width     : cols x0-2 .. x0+129 */
#define MW2 130     /* mag cols              : x0-1 .. x0+128       */

template<bool INTERIOR>
__device__ __forceinline__ void canny_body(
    const float* __restrict__ imgb,   /* img  + b*3*NPLANE */
    float* __restrict__ blb,          /* blur + b*3*NPLANE */
    float* __restrict__ out,
    int b, int x0, int y0, int t,
    float bh, float bv, float shb, float svb, float d0b, float d1b,
    float (*s_img)[CH][LW], float (*s_bl)[CH][LW], float (*s_mag)[LW])
{
    /* register rings (single column per thread) */
    float h0[CH], h1[CH], h2[CH], h3[CH], h4[CH];            /* vertical blur */
    float hs0[CH], hs1[CH], hs2[CH];                         /* sobel h-sums  */
    float hd0[CH], hd1[CH], hd2[CH];                         /* sobel h-diffs */
    #pragma unroll
    for (int c = 0; c < CH; c++) {
        h0[c] = h1[c] = h2[c] = h3[c] = h4[c] = 0.0f;
        hs0[c] = hs1[c] = hs2[c] = 0.0f;
        hd0[c] = hd1[c] = hd2[c] = 0.0f;
    }
    float pm = 0.0f, pgx = 0.0f, pgy = 0.0f;   /* last computed mag row, own col */

    const int gxl = x0 - 4 + t;                           /* img load col   */
    const bool cAok = INTERIOR || ((unsigned)gxl < (unsigned)W);
    const int colB = x0 - 2 + t;                          /* blurred col    */
    const bool cBok = INTERIOR || ((unsigned)colB < (unsigned)W);

    /* phase-C column map: t<128 -> col x0+t, t==128 -> halo x0-1, t==129 -> halo x0+128 */
    int ib, im; bool cMok;
    if (t < TX)       { ib = t + 2;  im = t + 1;  cMok = true; }
    else if (t == TX) { ib = 1;      im = 0;      cMok = INTERIOR || (x0 > 0); }
    else              { ib = TX + 2; im = TX + 1; cMok = INTERIOR || (x0 + TX < W); }

    const size_t pbase = (size_t)b * NPLANE + (size_t)y0 * W + x0 + t;

    float* gm_out     = out + (size_t)3 * NPIX;
    float* orient_out = out + (size_t)4 * NPIX;
    float* thin_out   = out + (size_t)5 * NPIX;
    float* thresh_out = out + (size_t)6 * NPIX;
    float* early_out  = out + (size_t)7 * NPIX;

    auto loadA = [&](int y_img, float (*si)[LW]) {
        if (t < LW) {
            if (INTERIOR) {
                const size_t ro = (size_t)y_img * W + gxl;
                #pragma unroll
                for (int c = 0; c < CH; c++)
                    si[c][t] = imgb[(size_t)c * NPLANE + ro];
            } else {
                const bool rAok = ((unsigned)y_img < (unsigned)H);
                const bool ok = rAok && cAok;
                const size_t ro = ok ? ((size_t)y_img * W + gxl) : 0;
                #pragma unroll
                for (int c = 0; c < CH; c++)
                    si[c][t] = ok ? imgb[(size_t)c * NPLANE + ro] : 0.0f;
            }
        }
    };

    auto phaseB = [&](int y_img, float (*si)[LW], float (*sb)[LW]) {
        const int yb = y_img - 2;
        if (t < BW) {
            const bool rAok = INTERIOR || ((unsigned)y_img < (unsigned)H);
            const bool rBok = INTERIOR || ((unsigned)yb < (unsigned)H);
            const bool wr = (yb >= y0) && (yb < y0 + TY) && (t >= 2) && (t < 2 + TX);
            float* wp = blb + ((size_t)yb * W + (x0 + t - 2));
            #pragma unroll
            for (int c = 0; c < CH; c++) {
                const float v0 = si[c][t],     v1 = si[c][t + 1],
                            v2 = si[c][t + 2], v3 = si[c][t + 3],
                            v4 = si[c][t + 4];
                float hn = G0 * (v0 + v4) + G1 * (v1 + v3) + v2 + bh;
                if (!INTERIOR && !rAok) hn = 0.0f;
                h0[c] = h1[c]; h1[c] = h2[c]; h2[c] = h3[c]; h3[c] = h4[c]; h4[c] = hn;
                const float B = G0 * (h0[c] + h4[c]) + G1 * (h1[c] + h3[c]) + h2[c] + bv;
                sb[c][t] = (INTERIOR || (rBok && cBok)) ? B : 0.0f;
                if (wr) wp[(size_t)c * NPLANE] = B;
            }
        }
    };

    auto phaseC = [&](int ym, float (*sb)[LW], float* mrow,
                      float& nm, float& ngx, float& ngy) {
        nm = 0.0f; ngx = 0.0f; ngy = 0.0f;
        if (t < MW2) {
            #pragma unroll
            for (int c = 0; c < CH; c++) {
                const float b0 = sb[c][ib - 1], b1 = sb[c][ib], b2 = sb[c][ib + 1];
                const float hsn = b0 + 2.0f * b1 + b2;
                const float hdn = b0 - b2;
                hs0[c] = hs1[c]; hs1[c] = hs2[c]; hs2[c] = hsn;
                hd0[c] = hd1[c]; hd1[c] = hd2[c]; hd2[c] = hdn;
                const float gxv = (hd0[c] + 2.0f * hd1[c]) + hd2[c] + shb;
                const float gyv = hs0[c] - hs2[c] + svb;
                nm += sqrtf(gxv * gxv + gyv * gyv);
                ngx += gxv; ngy += gyv;
            }
            const bool rMok = INTERIOR || ((unsigned)ym < (unsigned)H);
            if (!(rMok && cMok)) nm = 0.0f;
            mrow[im] = nm;
        }
    };

    auto phaseD = [&](int yo_off, float mag, float gx, float gy,
                      const float* magC, const float* magN) {
        if (t < TX) {
            const size_t p = pbase + (size_t)yo_off * W;

            gm_out[p] = mag;

            /* orientation: comparator fast path; exact fallback near the
               22.5/67.5 slope bands, on ay==0 with ax<=0, and in the near-pi
               wedge (reference's 180/3.14159 scale wraps past 180 there) */
            float ax = gx, ay = gy;
            if (ay < 0.0f) { ax = -ax; ay = -ay; }
            const float pxm = fabsf(ax);
            const float r1 = T1C * pxm;
            const float r2 = T2C * pxm;
            const bool nearb =
                (gx < 0.0f && fabsf(gy) <= WEDGE * (-gx)) ||
                (fabsf(ay - r1) <= BANDEPS * (ay + r1)) ||
                (fabsf(ay - r2) <= BANDEPS * (ay + r2)) ||
                (ay == 0.0f && ax <= 0.0f);
            int k; float orient;
            if (__builtin_expect(nearb, 0)) {
                float go = atan2f(gy, gx) * (180.0f / 3.14159f);
                if (go < 0.0f) go = 360.0f + go;
                go = fmodf(go, 180.0f);
                orient = rintf(go / 45.0f) * 45.0f;
                k = (int)(orient * (1.0f / 45.0f) + 0.5f);
            } else {
                if (ay >= r2)      k = 2;
                else if (ay >= r1) k = (ax > 0.0f) ? 1 : 3;
                else               k = (ax > 0.0f) ? 0 : 4;
                orient = 45.0f * (float)k;
            }
            orient_out[p] = orient;

            early_out[p] = (mag < 10.0f) ? 0.0f : mag;

            const int di = (k >= 1 && k <= 3) ? 1 : 0;
            const int dj = (k < 2) ? 1 : ((k == 2) ? 0 : -1);
            const float bias = (k < 4) ? d0b : d1b;

            const float nbv = (di ? magN : magC)[t + 1 + dj];  /* OOB already 0 */
            const float val = mag - nbv + bias;
            const float th = (val > 0.0f) ? mag : 0.0f;
            thin_out[p]   = th;
            thresh_out[p] = (th < 10.0f) ? 0.0f : th;
        }
    };

    /* one 2-row pair: A,A | sync | B,B | sync | C,C | sync | (D,D) */
    auto pair = [&](int i0, bool do_d) {
        const int i1 = i0 + 1;
        const int yA = y0 - 4 + i0;
        const int yB = y0 - 4 + i1;

        loadA(yA, s_img[0]);
        loadA(yB, s_img[1]);
        __syncthreads();

        phaseB(yA, s_img[0], s_bl[0]);
        phaseB(yB, s_img[1], s_bl[1]);
        __syncthreads();

        float nmA, ngxA, ngyA, nmB, ngxB, ngyB;
        phaseC(yA - 3, s_bl[0], s_mag[i0 & 3], nmA, ngxA, ngyA);
        phaseC(yB - 3, s_bl[1], s_mag[i1 & 3], nmB, ngxB, ngyB);
        __syncthreads();

        if (do_d) {
            phaseD(i0 - 8, pm, pgx, pgy, s_mag[(i0 - 1) & 3], s_mag[i0 & 3]);
            phaseD(i1 - 8, nmA, ngxA, ngyA, s_mag[i0 & 3], s_mag[i1 & 3]);
        }
        pm = nmB; pgx = ngxB; pgy = ngyB;
    };

    /* warmup: 4 pairs, no outputs */
    #pragma unroll
    for (int ii = 0; ii < 4; ii++)
        pair(2 * ii, false);

    /* steady state: 32 pairs with outputs; unroll 2 makes all ring slot
       indices compile-time and lets ptxas rename register rings */
    #pragma unroll 2
    for (int ii = 4; ii < (TY + 8) / 2; ii++)
        pair(2 * ii, true);
}

__global__ __launch_bounds__(NT) void canny_kernel(
    const float* __restrict__ img,
    const float* __restrict__ bh_p,  const float* __restrict__ bv_p,
    const float* __restrict__ shb_p, const float* __restrict__ svb_p,
    const float* __restrict__ d0b_p, const float* __restrict__ d1b_p,
    float* __restrict__ out)
{
    __shared__ float s_img[2][CH][LW];
    __shared__ float s_bl[2][CH][LW];
    __shared__ float s_mag[4][LW];

    const int b  = blockIdx.z;
    const int x0 = blockIdx.x * TX;
    const int y0 = blockIdx.y * TY;
    const int t  = threadIdx.x;

    const float bh  = __ldg(bh_p),  bv  = __ldg(bv_p);
    const float shb = __ldg(shb_p), svb = __ldg(svb_p);
    const float d0b = __ldg(d0b_p), d1b = __ldg(d1b_p);

    const float* imgb = img + (size_t)b * CH * NPLANE;
    float* blb = out + (size_t)b * CH * NPLANE;

    const bool interior = (x0 >= 4) && (x0 + TX + 4 <= W) &&
                          (y0 >= 4) && (y0 + TY + 4 <= H);

    if (interior)
        canny_body<true >(imgb, blb, out, b, x0, y0, t,
                          bh, bv, shb, svb, d0b, d1b, s_img, s_bl, s_mag);
    else
        canny_body<false>(imgb, blb, out, b, x0, y0, t,
                          bh, bv, shb, svb, d0b, d1b, s_img, s_bl, s_mag);
}

/* ================================================================== */
extern "C" void kernel_launch(void* const* d_in, const int* in_sizes, int n_in,
                              void* d_out, int out_size)
{
    const float* img = (const float*)d_in[0];
    const float* bh  = (const float*)d_in[1];
    const float* bv  = (const float*)d_in[2];
    const float* shb = (const float*)d_in[3];
    const float* svb = (const float*)d_in[4];
    const float* d0b = (const float*)d_in[5];
    const float* d1b = (const float*)d_in[6];

    dim3 grid(W / TX, H / TY, BATCH);
    canny_kernel<<<grid, NT>>>(img, bh, bv, shb, svb, d0b, d1b, (float*)d_out);

    (void)in_sizes; (void)n_in; (void)out_size;
}

// round 15
// speedup vs baseline: 1.0947x; 1.0947x over previous
#include <cuda_runtime.h>
#include <math.h>

#define H 1024
#define W 1024
#define BATCH 16
#define CH 3
#define NPLANE (H * W)
#define NPIX (BATCH * NPLANE)

#define G0 0.13533528323661270f  /* exp(-2)   */
#define G1 0.60653065971263342f  /* exp(-0.5) */
#define T1C 0.41421356237f       /* tan(22.5 deg) */
#define T2C 2.41421356237f       /* tan(67.5 deg) */
#define BANDEPS 1e-3f
#define WEDGE   1e-4f            /* near-pi wedge (ref wraps past 180) */

#define TX 128      /* tile width (outputs)  */
#define TY 64       /* tile height (outputs) */
#define NT 160      /* threads per block     */
#define LW 136      /* img row width loaded  : cols x0-4 .. x0+131 */
#define BW 132      /* blurred row width     : cols x0-2 .. x0+129 */
#define MW2 130     /* mag cols              : x0-1 .. x0+128       */

template<bool INTERIOR>
__device__ __forceinline__ void canny_body(
    const float* __restrict__ imgb,   /* img  + b*3*NPLANE */
    float* __restrict__ blb,          /* blur + b*3*NPLANE */
    float* __restrict__ out,
    int b, int x0, int y0, int t,
    float bh, float bv, float shb, float svb, float d0b, float d1b,
    float (*s_img)[CH][LW], float (*s_bl)[CH][LW], float (*s_mag)[LW])
{
    /* register rings (single column per thread) */
    float h0[CH], h1[CH], h2[CH], h3[CH], h4[CH];            /* vertical blur */
    float hs0[CH], hs1[CH], hs2[CH];                         /* sobel h-sums  */
    float hd0[CH], hd1[CH], hd2[CH];                         /* sobel h-diffs */
    #pragma unroll
    for (int c = 0; c < CH; c++) {
        h0[c] = h1[c] = h2[c] = h3[c] = h4[c] = 0.0f;
        hs0[c] = hs1[c] = hs2[c] = 0.0f;
        hd0[c] = hd1[c] = hd2[c] = 0.0f;
    }
    float pm = 0.0f, pgx = 0.0f, pgy = 0.0f;   /* last computed mag row, own col */

    const int gxl = x0 - 4 + t;                           /* img load col   */
    const bool cAok = INTERIOR || ((unsigned)gxl < (unsigned)W);
    const int colB = x0 - 2 + t;                          /* blurred col    */
    const bool cBok = INTERIOR || ((unsigned)colB < (unsigned)W);

    /* phase-C column map: t<128 -> col x0+t, t==128 -> halo x0-1, t==129 -> halo x0+128 */
    int ib, im; bool cMok;
    if (t < TX)       { ib = t + 2;  im = t + 1;  cMok = true; }
    else if (t == TX) { ib = 1;      im = 0;      cMok = INTERIOR || (x0 > 0); }
    else              { ib = TX + 2; im = TX + 1; cMok = INTERIOR || (x0 + TX < W); }

    const size_t pbase = (size_t)b * NPLANE + (size_t)y0 * W + x0 + t;

    float* gm_out     = out + (size_t)3 * NPIX;
    float* orient_out = out + (size_t)4 * NPIX;
    float* thin_out   = out + (size_t)5 * NPIX;
    float* thresh_out = out + (size_t)6 * NPIX;
    float* early_out  = out + (size_t)7 * NPIX;

    auto loadA = [&](int y_img, float (*si)[LW]) {
        if (t < LW) {
            if (INTERIOR) {
                const size_t ro = (size_t)y_img * W + gxl;
                #pragma unroll
                for (int c = 0; c < CH; c++)
                    si[c][t] = imgb[(size_t)c * NPLANE + ro];
            } else {
                const bool rAok = ((unsigned)y_img < (unsigned)H);
                const bool ok = rAok && cAok;
                const size_t ro = ok ? ((size_t)y_img * W + gxl) : 0;
                #pragma unroll
                for (int c = 0; c < CH; c++)
                    si[c][t] = ok ? imgb[(size_t)c * NPLANE + ro] : 0.0f;
            }
        }
    };

    auto phaseB = [&](int y_img, float (*si)[LW], float (*sb)[LW]) {
        const int yb = y_img - 2;
        if (t < BW) {
            const bool rAok = INTERIOR || ((unsigned)y_img < (unsigned)H);
            const bool rBok = INTERIOR || ((unsigned)yb < (unsigned)H);
            const bool wr = (yb >= y0) && (yb < y0 + TY) && (t >= 2) && (t < 2 + TX);
            float* wp = blb + ((size_t)yb * W + (x0 + t - 2));
            #pragma unroll
            for (int c = 0; c < CH; c++) {
                const float v0 = si[c][t],     v1 = si[c][t + 1],
                            v2 = si[c][t + 2], v3 = si[c][t + 3],
                            v4 = si[c][t + 4];
                float hn = G0 * (v0 + v4) + G1 * (v1 + v3) + v2 + bh;
                if (!INTERIOR && !rAok) hn = 0.0f;
                h0[c] = h1[c]; h1[c] = h2[c]; h2[c] = h3[c]; h3[c] = h4[c]; h4[c] = hn;
                const float B = G0 * (h0[c] + h4[c]) + G1 * (h1[c] + h3[c]) + h2[c] + bv;
                sb[c][t] = (INTERIOR || (rBok && cBok)) ? B : 0.0f;
                if (wr) __stcs(wp + (size_t)c * NPLANE, B);
            }
        }
    };

    auto phaseC = [&](int ym, float (*sb)[LW], float* mrow,
                      float& nm, float& ngx, float& ngy) {
        nm = 0.0f; ngx = 0.0f; ngy = 0.0f;
        if (t < MW2) {
            #pragma unroll
            for (int c = 0; c < CH; c++) {
                const float b0 = sb[c][ib - 1], b1 = sb[c][ib], b2 = sb[c][ib + 1];
                const float hsn = b0 + 2.0f * b1 + b2;
                const float hdn = b0 - b2;
                hs0[c] = hs1[c]; hs1[c] = hs2[c]; hs2[c] = hsn;
                hd0[c] = hd1[c]; hd1[c] = hd2[c]; hd2[c] = hdn;
                const float gxv = (hd0[c] + 2.0f * hd1[c]) + hd2[c] + shb;
                const float gyv = hs0[c] - hs2[c] + svb;
                nm += sqrtf(gxv * gxv + gyv * gyv);
                ngx += gxv; ngy += gyv;
            }
            const bool rMok = INTERIOR || ((unsigned)ym < (unsigned)H);
            if (!(rMok && cMok)) nm = 0.0f;
            mrow[im] = nm;
        }
    };

    auto phaseD = [&](int yo_off, float mag, float gx, float gy,
                      const float* magC, const float* magN) {
        if (t < TX) {
            const size_t p = pbase + (size_t)yo_off * W;

            __stcs(gm_out + p, mag);

            /* orientation: comparator fast path; exact fallback near the
               22.5/67.5 slope bands, on ay==0 with ax<=0, and in the near-pi
               wedge (reference's 180/3.14159 scale wraps past 180 there) */
            float ax = gx, ay = gy;
            if (ay < 0.0f) { ax = -ax; ay = -ay; }
            const float pxm = fabsf(ax);
            const float r1 = T1C * pxm;
            const float r2 = T2C * pxm;
            const bool nearb =
                (gx < 0.0f && fabsf(gy) <= WEDGE * (-gx)) ||
                (fabsf(ay - r1) <= BANDEPS * (ay + r1)) ||
                (fabsf(ay - r2) <= BANDEPS * (ay + r2)) ||
                (ay == 0.0f && ax <= 0.0f);
            int k; float orient;
            if (__builtin_expect(nearb, 0)) {
                float go = atan2f(gy, gx) * (180.0f / 3.14159f);
                if (go < 0.0f) go = 360.0f + go;
                go = fmodf(go, 180.0f);
                orient = rintf(go / 45.0f) * 45.0f;
                k = (int)(orient * (1.0f / 45.0f) + 0.5f);
            } else {
                if (ay >= r2)      k = 2;
                else if (ay >= r1) k = (ax > 0.0f) ? 1 : 3;
                else               k = (ax > 0.0f) ? 0 : 4;
                orient = 45.0f * (float)k;
            }
            __stcs(orient_out + p, orient);

            __stcs(early_out + p, (mag < 10.0f) ? 0.0f : mag);

            const int di = (k >= 1 && k <= 3) ? 1 : 0;
            const int dj = (k < 2) ? 1 : ((k == 2) ? 0 : -1);
            const float bias = (k < 4) ? d0b : d1b;

            const float nbv = (di ? magN : magC)[t + 1 + dj];  /* OOB already 0 */
            const float val = mag - nbv + bias;
            const float th = (val > 0.0f) ? mag : 0.0f;
            __stcs(thin_out + p, th);
            __stcs(thresh_out + p, (th < 10.0f) ? 0.0f : th);
        }
    };

    /* ---- main loop: 2 img rows per iteration, 3 barriers per pair ---- */
    #pragma unroll 1
    for (int ii = 0; ii < (TY + 8) / 2; ii++) {
        const int i0 = 2 * ii, i1 = 2 * ii + 1;
        const int yA = y0 - 4 + i0;
        const int yB = y0 - 4 + i1;

        loadA(yA, s_img[0]);
        loadA(yB, s_img[1]);
        __syncthreads();

        phaseB(yA, s_img[0], s_bl[0]);
        phaseB(yB, s_img[1], s_bl[1]);
        __syncthreads();

        float nmA, ngxA, ngyA, nmB, ngxB, ngyB;
        phaseC(yA - 3, s_bl[0], s_mag[i0 & 3], nmA, ngxA, ngyA);
        phaseC(yB - 3, s_bl[1], s_mag[i1 & 3], nmB, ngxB, ngyB);
        __syncthreads();

        if (ii >= 4) {
            phaseD(i0 - 8, pm, pgx, pgy, s_mag[(i0 - 1) & 3], s_mag[i0 & 3]);
            phaseD(i1 - 8, nmA, ngxA, ngyA, s_mag[i0 & 3], s_mag[i1 & 3]);
        }
        pm = nmB; pgx = ngxB; pgy = ngyB;
    }
}

__global__ __launch_bounds__(NT) void canny_kernel(
    const float* __restrict__ img,
    const float* __restrict__ bh_p,  const float* __restrict__ bv_p,
    const float* __restrict__ shb_p, const float* __restrict__ svb_p,
    const float* __restrict__ d0b_p, const float* __restrict__ d1b_p,
    float* __restrict__ out)
{
    __shared__ float s_img[2][CH][LW];
    __shared__ float s_bl[2][CH][LW];
    __shared__ float s_mag[4][LW];

    const int b  = blockIdx.z;
    const int x0 = blockIdx.x * TX;
    const int y0 = blockIdx.y * TY;
    const int t  = threadIdx.x;

    const float bh  = __ldg(bh_p),  bv  = __ldg(bv_p);
    const float shb = __ldg(shb_p), svb = __ldg(svb_p);
    const float d0b = __ldg(d0b_p), d1b = __ldg(d1b_p);

    const float* imgb = img + (size_t)b * CH * NPLANE;
    float* blb = out + (size_t)b * CH * NPLANE;

    const bool interior = (x0 >= 4) && (x0 + TX + 4 <= W) &&
                          (y0 >= 4) && (y0 + TY + 4 <= H);

    if (interior)
        canny_body<true >(imgb, blb, out, b, x0, y0, t,
                          bh, bv, shb, svb, d0b, d1b, s_img, s_bl, s_mag);
    else
        canny_body<false>(imgb, blb, out, b, x0, y0, t,
                          bh, bv, shb, svb, d0b, d1b, s_img, s_bl, s_mag);
}

/* ================================================================== */
extern "C" void kernel_launch(void* const* d_in, const int* in_sizes, int n_in,
                              void* d_out, int out_size)
{
    const float* img = (const float*)d_in[0];
    const float* bh  = (const float*)d_in[1];
    const float* bv  = (const float*)d_in[2];
    const float* shb = (const float*)d_in[3];
    const float* svb = (const float*)d_in[4];
    const float* d0b = (const float*)d_in[5];
    const float* d1b = (const float*)d_in[6];

    dim3 grid(W / TX, H / TY, BATCH);
    canny_kernel<<<grid, NT>>>(img, bh, bv, shb, svb, d0b, d1b, (float*)d_out);

    (void)in_sizes; (void)n_in; (void)out_size;
}